// round 1
// baseline (speedup 1.0000x reference)
#include <cuda_runtime.h>

#define NROWS 262144
#define DDIM  256
#define NCLUS 512
#define NPAIRS (NCLUS * (NCLUS - 1) / 2)   // 130816

#define CSTRIDE 32            // pad counters to 128B so L2-slice hash spreads them
#define ROWS_PER_CTA 2048
#define RANK_CTAS (NROWS / ROWS_PER_CTA)   // 128
#define MAXP 2048             // smem perm capacity in center kernel

// ---------------- scratch (static __device__, no allocs) ----------------
__device__ int   g_counts[NCLUS * CSTRIDE];
__device__ int   g_offsets[NCLUS];
__device__ int   g_rank[NROWS];
__device__ int   g_perm[NROWS];
__device__ float g_centers[NCLUS * DDIM];
__device__ float g_accum;

// ---------------- kernel 0: zero scratch ----------------
__global__ void k_init() {
    int t = blockIdx.x * blockDim.x + threadIdx.x;
    for (int i = t; i < NCLUS * CSTRIDE; i += gridDim.x * blockDim.x)
        g_counts[i] = 0;
    if (t == 0) g_accum = 0.0f;
}

// ---------------- kernel 1: per-CTA privatized label ranks ----------------
// Each CTA handles 2048 rows: smem-count + smem-rank, then one padded global
// atomic per (CTA, cluster) to claim a base, then write global ranks.
__global__ __launch_bounds__(256) void k_rank(const int* __restrict__ label) {
    __shared__ int s_cnt[NCLUS];
    __shared__ int s_base[NCLUS];
    const int tid  = threadIdx.x;
    const int base = blockIdx.x * ROWS_PER_CTA;

    for (int c = tid; c < NCLUS; c += 256) s_cnt[c] = 0;
    __syncthreads();

    int lab[ROWS_PER_CTA / 256];
    int lrk[ROWS_PER_CTA / 256];
#pragma unroll
    for (int k = 0; k < ROWS_PER_CTA / 256; k++) {
        int i = base + tid + k * 256;
        int l = label[i];
        lab[k] = l;
        lrk[k] = atomicAdd(&s_cnt[l], 1);
    }
    __syncthreads();

    for (int c = tid; c < NCLUS; c += 256) {
        int n = s_cnt[c];
        s_base[c] = (n > 0) ? atomicAdd(&g_counts[c * CSTRIDE], n) : 0;
    }
    __syncthreads();

#pragma unroll
    for (int k = 0; k < ROWS_PER_CTA / 256; k++) {
        int i = base + tid + k * 256;
        g_rank[i] = s_base[lab[k]] + lrk[k];
    }
}

// ---------------- kernel 2: exclusive prefix over 512 counts ----------------
__global__ __launch_bounds__(NCLUS) void k_prefix() {
    __shared__ int s[NCLUS];
    int t = threadIdx.x;
    int own = g_counts[t * CSTRIDE];
    s[t] = own;
    __syncthreads();
    for (int off = 1; off < NCLUS; off <<= 1) {
        int v = 0;
        if (t >= off) v = s[t - off];
        __syncthreads();
        if (t >= off) s[t] += v;
        __syncthreads();
    }
    g_offsets[t] = s[t] - own;   // exclusive
}

// ---------------- kernel 3: scatter permutation ----------------
__global__ __launch_bounds__(512) void k_scatter(const int* __restrict__ label) {
    int i = blockIdx.x * blockDim.x + threadIdx.x;
    if (i < NROWS) {
        int l = label[i];
        g_perm[g_offsets[l] + g_rank[i]] = i;
    }
}

// ---------------- kernel 4: per-cluster gather-mean (HBM-bound hot path) ----
__global__ __launch_bounds__(256) void k_center(const float* __restrict__ M) {
    __shared__ int sperm[MAXP];
    const int c     = blockIdx.x;
    const int start = g_offsets[c];
    const int cnt   = g_counts[c * CSTRIDE];
    const int t     = threadIdx.x;     // column 0..255

    float a0 = 0.f, a1 = 0.f, a2 = 0.f, a3 = 0.f;

    if (cnt <= MAXP) {
        for (int r = t; r < cnt; r += 256) sperm[r] = g_perm[start + r];
        __syncthreads();
        int r = 0;
        for (; r + 4 <= cnt; r += 4) {
            a0 += M[sperm[r + 0] * DDIM + t];
            a1 += M[sperm[r + 1] * DDIM + t];
            a2 += M[sperm[r + 2] * DDIM + t];
            a3 += M[sperm[r + 3] * DDIM + t];
        }
        for (; r < cnt; r++) a0 += M[sperm[r] * DDIM + t];
    } else {  // safety fallback (never hit with ~512-mean counts)
        int r = 0;
        for (; r + 4 <= cnt; r += 4) {
            a0 += M[g_perm[start + r + 0] * DDIM + t];
            a1 += M[g_perm[start + r + 1] * DDIM + t];
            a2 += M[g_perm[start + r + 2] * DDIM + t];
            a3 += M[g_perm[start + r + 3] * DDIM + t];
        }
        for (; r < cnt; r++) a0 += M[g_perm[start + r] * DDIM + t];
    }
    float s = (a0 + a1) + (a2 + a3);
    float denom = (float)(cnt > 0 ? cnt : 1);
    g_centers[c * DDIM + t] = s / denom;
}

// ---------------- kernel 5: tiled pdist + sum ----------------
// 32x32 pair tiles, 16x16 threads, 2x2 register blocking, D chunks of 64.
#define PT 32
#define DCH 64
#define NT (NCLUS / PT)   // 16 tiles -> 136 blocks
__global__ __launch_bounds__(256) void k_pdist() {
    __shared__ float Ci[PT][DCH + 1];
    __shared__ float Cj[PT][DCH + 1];
    __shared__ float red[8];

    // decode flattened upper-triangular block index -> (bi, bj)
    int b = blockIdx.x;
    int bi = 0, nb = NT;
    while (b >= nb) { b -= nb; bi++; nb--; }
    int bj = bi + b;
    const int i0 = bi * PT, j0 = bj * PT;

    const int tid = threadIdx.x;
    const int tx = tid & 15, ty = tid >> 4;

    float s00 = 0.f, s01 = 0.f, s10 = 0.f, s11 = 0.f;

    for (int dbase = 0; dbase < DDIM; dbase += DCH) {
        for (int idx = tid; idx < PT * DCH; idx += 256) {
            int r = idx / DCH, col = idx % DCH;
            Ci[r][col] = g_centers[(i0 + r) * DDIM + dbase + col];
            Cj[r][col] = g_centers[(j0 + r) * DDIM + dbase + col];
        }
        __syncthreads();
#pragma unroll 8
        for (int d = 0; d < DCH; d++) {
            float ia = Ci[2 * ty + 0][d];
            float ib = Ci[2 * ty + 1][d];
            float ja = Cj[2 * tx + 0][d];
            float jb = Cj[2 * tx + 1][d];
            float d00 = ia - ja; s00 += d00 * d00;
            float d01 = ia - jb; s01 += d01 * d01;
            float d10 = ib - ja; s10 += d10 * d10;
            float d11 = ib - jb; s11 += d11 * d11;
        }
        __syncthreads();
    }

    float local = 0.f;
    {
        int gi0 = i0 + 2 * ty, gi1 = gi0 + 1;
        int gj0 = j0 + 2 * tx, gj1 = gj0 + 1;
        if (gj0 > gi0) local += sqrtf(fmaxf(s00, 1e-12f));
        if (gj1 > gi0) local += sqrtf(fmaxf(s01, 1e-12f));
        if (gj0 > gi1) local += sqrtf(fmaxf(s10, 1e-12f));
        if (gj1 > gi1) local += sqrtf(fmaxf(s11, 1e-12f));
    }
    // warp reduce
#pragma unroll
    for (int off = 16; off > 0; off >>= 1)
        local += __shfl_down_sync(0xffffffffu, local, off);
    if ((tid & 31) == 0) red[tid >> 5] = local;
    __syncthreads();
    if (tid == 0) {
        float blk = 0.f;
#pragma unroll
        for (int w = 0; w < 8; w++) blk += red[w];
        atomicAdd(&g_accum, blk);
    }
}

// ---------------- kernel 6: finalize ----------------
__global__ void k_final(float* __restrict__ out) {
    out[0] = -g_accum / (float)NPAIRS;
}

extern "C" void kernel_launch(void* const* d_in, const int* in_sizes, int n_in,
                              void* d_out, int out_size) {
    const float* matrix = (const float*)d_in[0];
    const int*   label  = (const int*)d_in[1];
    float* out = (float*)d_out;

    k_init<<<32, 512>>>();
    k_rank<<<RANK_CTAS, 256>>>(label);
    k_prefix<<<1, NCLUS>>>();
    k_scatter<<<NROWS / 512, 512>>>(label);
    k_center<<<NCLUS, 256>>>(matrix);
    k_pdist<<<NT * (NT + 1) / 2, 256>>>();
    k_final<<<1, 1>>>(out);
}

// round 2
// speedup vs baseline: 1.0465x; 1.0465x over previous
#include <cuda_runtime.h>

#define NROWS 262144
#define DDIM  256
#define NCLUS 512
#define NPAIRS (NCLUS * (NCLUS - 1) / 2)   // 130816

#define CSTRIDE 32            // pad counters to 128B so L2-slice hash spreads them
#define ROWS_PER_CTA 2048
#define RANK_CTAS (NROWS / ROWS_PER_CTA)   // 128
#define MAXP 2048             // smem perm capacity in center kernel

// ---------------- scratch (static __device__, zero-initialized) ----------------
__device__ int   g_counts[NCLUS * CSTRIDE];  // atomic counters; re-zeroed by k_prefix
__device__ int   g_cnt[NCLUS];               // stable per-cluster counts
__device__ int   g_offsets[NCLUS];
__device__ int   g_rank[NROWS];
__device__ int   g_perm[NROWS];
__device__ float g_centers[NCLUS * DDIM];
__device__ float g_accum;                    // re-zeroed by k_prefix each launch
__device__ int   g_done;                     // reset by last pdist CTA

// ---------------- kernel 1: per-CTA privatized label ranks ----------------
__global__ __launch_bounds__(256) void k_rank(const int* __restrict__ label) {
    __shared__ int s_cnt[NCLUS];
    __shared__ int s_base[NCLUS];
    const int tid  = threadIdx.x;
    const int base = blockIdx.x * ROWS_PER_CTA;

    for (int c = tid; c < NCLUS; c += 256) s_cnt[c] = 0;
    __syncthreads();

    int lab[ROWS_PER_CTA / 256];
    int lrk[ROWS_PER_CTA / 256];
#pragma unroll
    for (int k = 0; k < ROWS_PER_CTA / 256; k++) {
        int i = base + tid + k * 256;
        int l = __ldg(&label[i]);
        lab[k] = l;
        lrk[k] = atomicAdd(&s_cnt[l], 1);
    }
    __syncthreads();

    for (int c = tid; c < NCLUS; c += 256) {
        int n = s_cnt[c];
        s_base[c] = (n > 0) ? atomicAdd(&g_counts[c * CSTRIDE], n) : 0;
    }
    __syncthreads();

#pragma unroll
    for (int k = 0; k < ROWS_PER_CTA / 256; k++) {
        int i = base + tid + k * 256;
        g_rank[i] = s_base[lab[k]] + lrk[k];
    }
}

// ---------------- kernel 2: prefix over 512 counts; SELF-CLEANING ----------
// Reads the atomic counters, then zeroes them (and g_accum) so the next graph
// replay starts from a clean state without a separate init kernel.
__global__ __launch_bounds__(NCLUS) void k_prefix() {
    __shared__ int s[NCLUS];
    int t = threadIdx.x;
    int own = g_counts[t * CSTRIDE];
    s[t] = own;
    __syncthreads();
    for (int off = 1; off < NCLUS; off <<= 1) {
        int v = 0;
        if (t >= off) v = s[t - off];
        __syncthreads();
        if (t >= off) s[t] += v;
        __syncthreads();
    }
    g_offsets[t] = s[t] - own;   // exclusive
    g_cnt[t]     = own;
    g_counts[t * CSTRIDE] = 0;   // clean for next replay
    if (t == 0) g_accum = 0.0f;
}

// ---------------- kernel 3: scatter permutation (ILP=4) ----------------
__global__ __launch_bounds__(256) void k_scatter(const int* __restrict__ label) {
    const int base = blockIdx.x * 1024 + threadIdx.x;
    int l[4], rk[4], of[4];
#pragma unroll
    for (int k = 0; k < 4; k++) {
        int i = base + k * 256;
        l[k]  = __ldg(&label[i]);
        rk[k] = g_rank[i];
    }
#pragma unroll
    for (int k = 0; k < 4; k++) of[k] = __ldg(&g_offsets[l[k]]);
#pragma unroll
    for (int k = 0; k < 4; k++) {
        int i = base + k * 256;
        g_perm[of[k] + rk[k]] = i;
    }
}

// ---------------- kernel 4: per-cluster gather-mean (float4, MLP=4) --------
__global__ __launch_bounds__(256) void k_center(const float* __restrict__ M) {
    __shared__ int    sperm[MAXP];
    __shared__ float4 sred[3][64];
    const int c     = blockIdx.x;
    const int start = g_offsets[c];
    const int cnt   = g_cnt[c];
    const int t     = threadIdx.x;
    const int grp   = t >> 6;      // 0..3: row phase
    const int col4  = t & 63;      // float4 column

    const float4* __restrict__ Mv = (const float4*)M;

    float4 a0 = {0,0,0,0}, a1 = {0,0,0,0}, a2 = {0,0,0,0}, a3 = {0,0,0,0};

    if (cnt <= MAXP) {
        for (int r = t; r < cnt; r += 256) sperm[r] = g_perm[start + r];
        __syncthreads();
        int r = grp;
        for (; r + 12 < cnt; r += 16) {
            size_t i0 = (size_t)sperm[r]      * 64;
            size_t i1 = (size_t)sperm[r + 4]  * 64;
            size_t i2 = (size_t)sperm[r + 8]  * 64;
            size_t i3 = (size_t)sperm[r + 12] * 64;
            float4 v0 = Mv[i0 + col4];
            float4 v1 = Mv[i1 + col4];
            float4 v2 = Mv[i2 + col4];
            float4 v3 = Mv[i3 + col4];
            a0.x += v0.x; a0.y += v0.y; a0.z += v0.z; a0.w += v0.w;
            a1.x += v1.x; a1.y += v1.y; a1.z += v1.z; a1.w += v1.w;
            a2.x += v2.x; a2.y += v2.y; a2.z += v2.z; a2.w += v2.w;
            a3.x += v3.x; a3.y += v3.y; a3.z += v3.z; a3.w += v3.w;
        }
        for (; r < cnt; r += 4) {
            float4 v = Mv[(size_t)sperm[r] * 64 + col4];
            a0.x += v.x; a0.y += v.y; a0.z += v.z; a0.w += v.w;
        }
    } else {  // safety fallback
        int r = grp;
        for (; r < cnt; r += 4) {
            float4 v = Mv[(size_t)g_perm[start + r] * 64 + col4];
            a0.x += v.x; a0.y += v.y; a0.z += v.z; a0.w += v.w;
        }
        __syncthreads();  // match barrier count across branch (none taken in practice)
    }

    float4 acc;
    acc.x = (a0.x + a1.x) + (a2.x + a3.x);
    acc.y = (a0.y + a1.y) + (a2.y + a3.y);
    acc.z = (a0.z + a1.z) + (a2.z + a3.z);
    acc.w = (a0.w + a1.w) + (a2.w + a3.w);

    if (grp > 0) sred[grp - 1][col4] = acc;
    __syncthreads();
    if (grp == 0) {
        float4 b0 = sred[0][col4], b1 = sred[1][col4], b2 = sred[2][col4];
        acc.x += b0.x + b1.x + b2.x;
        acc.y += b0.y + b1.y + b2.y;
        acc.z += b0.z + b1.z + b2.z;
        acc.w += b0.w + b1.w + b2.w;
        float inv = 1.0f / (float)(cnt > 0 ? cnt : 1);
        acc.x *= inv; acc.y *= inv; acc.z *= inv; acc.w *= inv;
        ((float4*)(g_centers + c * DDIM))[col4] = acc;
    }
}

// ---------------- kernel 5: tiled pdist + sum + fused finalize --------------
#define PT 32
#define DCH 64
#define NT (NCLUS / PT)                 // 16 -> 136 blocks
#define PDIST_BLOCKS (NT * (NT + 1) / 2)
__global__ __launch_bounds__(256) void k_pdist(float* __restrict__ out) {
    __shared__ float Ci[PT][DCH + 1];
    __shared__ float Cj[PT][DCH + 1];
    __shared__ float red[8];

    int b = blockIdx.x;
    int bi = 0, nb = NT;
    while (b >= nb) { b -= nb; bi++; nb--; }
    int bj = bi + b;
    const int i0 = bi * PT, j0 = bj * PT;

    const int tid = threadIdx.x;
    const int tx = tid & 15, ty = tid >> 4;

    float s00 = 0.f, s01 = 0.f, s10 = 0.f, s11 = 0.f;

    for (int dbase = 0; dbase < DDIM; dbase += DCH) {
        for (int idx = tid; idx < PT * DCH; idx += 256) {
            int r = idx / DCH, col = idx % DCH;
            Ci[r][col] = g_centers[(i0 + r) * DDIM + dbase + col];
            Cj[r][col] = g_centers[(j0 + r) * DDIM + dbase + col];
        }
        __syncthreads();
#pragma unroll 8
        for (int d = 0; d < DCH; d++) {
            float ia = Ci[2 * ty + 0][d];
            float ib = Ci[2 * ty + 1][d];
            float ja = Cj[2 * tx + 0][d];
            float jb = Cj[2 * tx + 1][d];
            float d00 = ia - ja; s00 += d00 * d00;
            float d01 = ia - jb; s01 += d01 * d01;
            float d10 = ib - ja; s10 += d10 * d10;
            float d11 = ib - jb; s11 += d11 * d11;
        }
        __syncthreads();
    }

    float local = 0.f;
    {
        int gi0 = i0 + 2 * ty, gi1 = gi0 + 1;
        int gj0 = j0 + 2 * tx, gj1 = gj0 + 1;
        if (gj0 > gi0) local += sqrtf(fmaxf(s00, 1e-12f));
        if (gj1 > gi0) local += sqrtf(fmaxf(s01, 1e-12f));
        if (gj0 > gi1) local += sqrtf(fmaxf(s10, 1e-12f));
        if (gj1 > gi1) local += sqrtf(fmaxf(s11, 1e-12f));
    }
#pragma unroll
    for (int off = 16; off > 0; off >>= 1)
        local += __shfl_down_sync(0xffffffffu, local, off);
    if ((tid & 31) == 0) red[tid >> 5] = local;
    __syncthreads();
    if (tid == 0) {
        float blk = 0.f;
#pragma unroll
        for (int w = 0; w < 8; w++) blk += red[w];
        atomicAdd(&g_accum, blk);
        __threadfence();
        int prev = atomicAdd(&g_done, 1);
        if (prev == PDIST_BLOCKS - 1) {
            g_done = 0;                          // reset for next replay
            out[0] = -g_accum / (float)NPAIRS;   // fused finalize
        }
    }
}

extern "C" void kernel_launch(void* const* d_in, const int* in_sizes, int n_in,
                              void* d_out, int out_size) {
    const float* matrix = (const float*)d_in[0];
    const int*   label  = (const int*)d_in[1];
    float* out = (float*)d_out;

    k_rank<<<RANK_CTAS, 256>>>(label);
    k_prefix<<<1, NCLUS>>>();
    k_scatter<<<NROWS / 1024, 256>>>(label);
    k_center<<<NCLUS, 256>>>(matrix);
    k_pdist<<<PDIST_BLOCKS, 256>>>(out);
}

// round 3
// speedup vs baseline: 1.1470x; 1.0961x over previous
#include <cuda_runtime.h>

#define NROWS 262144
#define DDIM  256
#define NCLUS 512
#define NPAIRS (NCLUS * (NCLUS - 1) / 2)   // 130816

#define CSTRIDE 32            // pad counters to 128B so L2-slice hash spreads them
#define ROWS_PER_CTA 2048
#define SORT_CTAS (NROWS / ROWS_PER_CTA)   // 128 (< 148 SMs: all co-resident)
#define SEGS 4
#define CENTER_CTAS (NCLUS * SEGS)         // 2048

// ---------------- scratch (static __device__, zero-initialized) -------------
__device__ int      g_counts[NCLUS * CSTRIDE];  // atomic counters; re-zeroed in k_sort
__device__ int      g_cnt[NCLUS];
__device__ int      g_offsets[NCLUS];
__device__ float    g_inv[NCLUS];
__device__ int      g_perm[NROWS];
__device__ float    g_sum[NCLUS * DDIM];        // center sums; zeroed in k_sort
__device__ float    g_accum;
__device__ int      g_done;
__device__ unsigned g_barrier;                  // monotone grid-barrier counter

// Grid barrier, replay-safe: counter never resets; each barrier instance is
// identified by ticket/128. Requires all SORT_CTAS co-resident (true: 128<148).
__device__ __forceinline__ void grid_bar() {
    __syncthreads();
    if (threadIdx.x == 0) {
        __threadfence();
        unsigned t = atomicAdd(&g_barrier, 1u);
        unsigned target = (t / SORT_CTAS + 1u) * SORT_CTAS;
        while ((int)(*(volatile unsigned*)&g_barrier - target) < 0) { }
        __threadfence();
    }
    __syncthreads();
}

// ---------------- kernel 1: fused rank + prefix + scatter -------------------
__global__ __launch_bounds__(256) void k_sort(const int* __restrict__ label) {
    __shared__ int s_cnt[NCLUS];    // local counts, then reused as global offsets
    __shared__ int s_base[NCLUS];   // this CTA's base within each cluster
    __shared__ int s_pref[NCLUS];
    const int tid  = threadIdx.x;
    const int base = blockIdx.x * ROWS_PER_CTA;

    for (int c = tid; c < NCLUS; c += 256) s_cnt[c] = 0;
    __syncthreads();

    // phase 1: local histogram + local ranks (kept in registers)
    int lab[8], lrk[8];
#pragma unroll
    for (int k = 0; k < 8; k++) {
        int i = base + k * 256 + tid;
        int l = __ldg(&label[i]);
        lab[k] = l;
        lrk[k] = atomicAdd(&s_cnt[l], 1);
    }
    __syncthreads();

    // claim global per-cluster bases; overlap with zeroing g_sum slice
    for (int c = tid; c < NCLUS; c += 256) {
        int n = s_cnt[c];
        s_base[c] = (n > 0) ? atomicAdd(&g_counts[c * CSTRIDE], n) : 0;
    }
    {   // zero this CTA's 1024-float slice of g_sum (512KB total / 128 CTAs)
        float* z = g_sum + blockIdx.x * (NCLUS * DDIM / SORT_CTAS);
#pragma unroll
        for (int j = 0; j < 4; j++) z[j * 256 + tid] = 0.0f;
    }
    if (blockIdx.x == 0 && tid == 0) g_accum = 0.0f;

    grid_bar();  // all global count atomics complete

    // every CTA computes the 512-wide prefix locally (Hillis-Steele, 2/thread)
    const int c0 = tid, c1 = tid + 256;
    int cntA = g_counts[c0 * CSTRIDE];
    int cntB = g_counts[c1 * CSTRIDE];
    s_pref[c0] = cntA;
    s_pref[c1] = cntB;
    __syncthreads();
    for (int off = 1; off < NCLUS; off <<= 1) {
        int v0 = (c0 >= off) ? s_pref[c0 - off] : 0;
        int v1 = (c1 >= off) ? s_pref[c1 - off] : 0;
        __syncthreads();
        s_pref[c0] += v0;
        s_pref[c1] += v1;
        __syncthreads();
    }
    s_cnt[c0] = s_pref[c0] - cntA;   // exclusive offsets (s_cnt reused)
    s_cnt[c1] = s_pref[c1] - cntB;

    grid_bar();  // all CTAs have read g_counts; safe to reset

    if (tid < SEGS) g_counts[(blockIdx.x * SEGS + tid) * CSTRIDE] = 0;
    if (blockIdx.x == 0) {
        g_offsets[c0] = s_cnt[c0];   g_offsets[c1] = s_cnt[c1];
        g_cnt[c0] = cntA;            g_cnt[c1] = cntB;
        g_inv[c0] = 1.0f / (float)(cntA > 0 ? cntA : 1);
        g_inv[c1] = 1.0f / (float)(cntB > 0 ? cntB : 1);
    }
    __syncthreads();

    // phase 2: scatter permutation (labels/ranks still in registers)
#pragma unroll
    for (int k = 0; k < 8; k++) {
        int i = base + k * 256 + tid;
        int c = lab[k];
        g_perm[s_cnt[c] + s_base[c] + lrk[k]] = i;
    }
}

// ---------------- kernel 2: segmented gather-sum (HBM hot path) -------------
__global__ __launch_bounds__(256) void k_center(const float* __restrict__ M) {
    __shared__ int    sperm[1024];
    __shared__ float4 sred[3][64];
    const int c     = blockIdx.x >> 2;
    const int seg   = blockIdx.x & 3;
    const int start = g_offsets[c];
    const int cnt   = g_cnt[c];
    const int s0    = (cnt * seg) >> 2;
    const int s1    = (cnt * (seg + 1)) >> 2;
    const int n     = s1 - s0;
    const int t     = threadIdx.x;
    const int grp   = t >> 6;      // 0..3: row phase
    const int col4  = t & 63;      // float4 column

    const float4* __restrict__ Mv = (const float4*)M;
    float4 a0 = {0,0,0,0}, a1 = {0,0,0,0}, a2 = {0,0,0,0}, a3 = {0,0,0,0};

    if (n <= 1024) {
        for (int r = t; r < n; r += 256) sperm[r] = g_perm[start + s0 + r];
        __syncthreads();
        int r = grp;
        for (; r + 12 < n; r += 16) {
            float4 v0 = Mv[(size_t)sperm[r]      * 64 + col4];
            float4 v1 = Mv[(size_t)sperm[r + 4]  * 64 + col4];
            float4 v2 = Mv[(size_t)sperm[r + 8]  * 64 + col4];
            float4 v3 = Mv[(size_t)sperm[r + 12] * 64 + col4];
            a0.x += v0.x; a0.y += v0.y; a0.z += v0.z; a0.w += v0.w;
            a1.x += v1.x; a1.y += v1.y; a1.z += v1.z; a1.w += v1.w;
            a2.x += v2.x; a2.y += v2.y; a2.z += v2.z; a2.w += v2.w;
            a3.x += v3.x; a3.y += v3.y; a3.z += v3.z; a3.w += v3.w;
        }
        for (; r < n; r += 4) {
            float4 v = Mv[(size_t)sperm[r] * 64 + col4];
            a0.x += v.x; a0.y += v.y; a0.z += v.z; a0.w += v.w;
        }
    } else {  // safety fallback (statistically unreachable)
        for (int r = grp; r < n; r += 4) {
            float4 v = Mv[(size_t)g_perm[start + s0 + r] * 64 + col4];
            a0.x += v.x; a0.y += v.y; a0.z += v.z; a0.w += v.w;
        }
        __syncthreads();
    }

    float4 acc;
    acc.x = (a0.x + a1.x) + (a2.x + a3.x);
    acc.y = (a0.y + a1.y) + (a2.y + a3.y);
    acc.z = (a0.z + a1.z) + (a2.z + a3.z);
    acc.w = (a0.w + a1.w) + (a2.w + a3.w);

    if (grp > 0) sred[grp - 1][col4] = acc;
    __syncthreads();
    if (grp == 0) {
        float4 b0 = sred[0][col4], b1 = sred[1][col4], b2 = sred[2][col4];
        acc.x += b0.x + b1.x + b2.x;
        acc.y += b0.y + b1.y + b2.y;
        acc.z += b0.z + b1.z + b2.z;
        acc.w += b0.w + b1.w + b2.w;
        float* dst = g_sum + c * DDIM + col4 * 4;
        atomicAdd(dst + 0, acc.x);
        atomicAdd(dst + 1, acc.y);
        atomicAdd(dst + 2, acc.z);
        atomicAdd(dst + 3, acc.w);
    }
}

// ---------------- kernel 3: tiled pdist (divide fused into load) + finalize -
#define PT 32
#define DCH 64
#define NT (NCLUS / PT)                 // 16 -> 136 blocks
#define PDIST_BLOCKS (NT * (NT + 1) / 2)
__global__ __launch_bounds__(256) void k_pdist(float* __restrict__ out) {
    __shared__ float Ci[PT][DCH + 1];
    __shared__ float Cj[PT][DCH + 1];
    __shared__ float red[8];

    int b = blockIdx.x;
    int bi = 0, nb = NT;
    while (b >= nb) { b -= nb; bi++; nb--; }
    int bj = bi + b;
    const int i0 = bi * PT, j0 = bj * PT;

    const int tid = threadIdx.x;
    const int tx = tid & 15, ty = tid >> 4;

    float s00 = 0.f, s01 = 0.f, s10 = 0.f, s11 = 0.f;

    for (int dbase = 0; dbase < DDIM; dbase += DCH) {
        for (int idx = tid; idx < PT * DCH; idx += 256) {
            int r = idx / DCH, col = idx % DCH;
            Ci[r][col] = g_sum[(i0 + r) * DDIM + dbase + col] * g_inv[i0 + r];
            Cj[r][col] = g_sum[(j0 + r) * DDIM + dbase + col] * g_inv[j0 + r];
        }
        __syncthreads();
#pragma unroll 8
        for (int d = 0; d < DCH; d++) {
            float ia = Ci[2 * ty + 0][d];
            float ib = Ci[2 * ty + 1][d];
            float ja = Cj[2 * tx + 0][d];
            float jb = Cj[2 * tx + 1][d];
            float d00 = ia - ja; s00 += d00 * d00;
            float d01 = ia - jb; s01 += d01 * d01;
            float d10 = ib - ja; s10 += d10 * d10;
            float d11 = ib - jb; s11 += d11 * d11;
        }
        __syncthreads();
    }

    float local = 0.f;
    {
        int gi0 = i0 + 2 * ty, gi1 = gi0 + 1;
        int gj0 = j0 + 2 * tx, gj1 = gj0 + 1;
        if (gj0 > gi0) local += sqrtf(fmaxf(s00, 1e-12f));
        if (gj1 > gi0) local += sqrtf(fmaxf(s01, 1e-12f));
        if (gj0 > gi1) local += sqrtf(fmaxf(s10, 1e-12f));
        if (gj1 > gi1) local += sqrtf(fmaxf(s11, 1e-12f));
    }
#pragma unroll
    for (int off = 16; off > 0; off >>= 1)
        local += __shfl_down_sync(0xffffffffu, local, off);
    if ((tid & 31) == 0) red[tid >> 5] = local;
    __syncthreads();
    if (tid == 0) {
        float blk = 0.f;
#pragma unroll
        for (int w = 0; w < 8; w++) blk += red[w];
        atomicAdd(&g_accum, blk);
        __threadfence();
        int prev = atomicAdd(&g_done, 1);
        if (prev == PDIST_BLOCKS - 1) {
            g_done = 0;
            out[0] = -g_accum / (float)NPAIRS;
        }
    }
}

extern "C" void kernel_launch(void* const* d_in, const int* in_sizes, int n_in,
                              void* d_out, int out_size) {
    const float* matrix = (const float*)d_in[0];
    const int*   label  = (const int*)d_in[1];
    float* out = (float*)d_out;

    k_sort<<<SORT_CTAS, 256>>>(label);
    k_center<<<CENTER_CTAS, 256>>>(matrix);
    k_pdist<<<PDIST_BLOCKS, 256>>>(out);
}

// round 4
// speedup vs baseline: 1.3252x; 1.1553x over previous
#include <cuda_runtime.h>

#define NROWS 262144
#define DDIM  256
#define NCLUS 512
#define NPAIRS (NCLUS * (NCLUS - 1) / 2)   // 130816

#define CSTRIDE 32            // pad counters to 128B so L2-slice hash spreads them
#define ROWS_PER_CTA 2048
#define SORT_CTAS (NROWS / ROWS_PER_CTA)   // 128 (< 148 SMs: all co-resident)
#define SORT_THREADS 512
#define SORT_RPT (ROWS_PER_CTA / SORT_THREADS)  // 4
#define SEGS 4
#define CENTER_CTAS (NCLUS * SEGS)         // 2048

// ---------------- scratch (static __device__, zero-initialized) -------------
__device__ int      g_counts[NCLUS * CSTRIDE];  // atomic counters; re-zeroed in k_center
__device__ int      g_cnt[NCLUS];
__device__ int      g_offsets[NCLUS];
__device__ float    g_inv[NCLUS];
__device__ int      g_perm[NROWS];
__device__ float    g_sum[NCLUS * DDIM];        // center sums; zeroed in k_sort
__device__ float    g_accum;
__device__ int      g_done;
__device__ unsigned g_barrier;                  // monotone grid-barrier counter

// Grid barrier, replay-safe: counter never resets; each barrier instance is
// identified by ticket/128. Requires all SORT_CTAS co-resident (true: 128<148).
__device__ __forceinline__ void grid_bar() {
    __syncthreads();
    if (threadIdx.x == 0) {
        __threadfence();
        unsigned t = atomicAdd(&g_barrier, 1u);
        unsigned target = (t / SORT_CTAS + 1u) * SORT_CTAS;
        while ((int)(*(volatile unsigned*)&g_barrier - target) < 0) { }
        __threadfence();
    }
    __syncthreads();
}

// ---------------- kernel 1: fused rank + prefix + scatter -------------------
// 512 threads (16 warps/SM), single grid barrier, warp-shuffle prefix scan.
__global__ __launch_bounds__(SORT_THREADS) void k_sort(const int* __restrict__ label) {
    __shared__ int s_cnt[NCLUS];    // local histogram
    __shared__ int s_base[NCLUS];   // this CTA's claimed base within each cluster
    __shared__ int s_off[NCLUS];    // global exclusive offsets
    __shared__ int s_wsum[16];
    const int tid  = threadIdx.x;
    const int base = blockIdx.x * ROWS_PER_CTA;

    s_cnt[tid] = 0;                 // 512 threads, 512 clusters: one each
    __syncthreads();

    // phase 1: local histogram + local ranks (kept in registers)
    int lab[SORT_RPT], lrk[SORT_RPT];
#pragma unroll
    for (int k = 0; k < SORT_RPT; k++) {
        int i = base + k * SORT_THREADS + tid;
        int l = __ldg(&label[i]);
        lab[k] = l;
        lrk[k] = atomicAdd(&s_cnt[l], 1);
    }
    __syncthreads();

    // claim global per-cluster base (one counter per thread)
    {
        int n = s_cnt[tid];
        s_base[tid] = (n > 0) ? atomicAdd(&g_counts[tid * CSTRIDE], n) : 0;
    }
    // zero this CTA's 1024-float slice of g_sum while waiting
    {
        float* z = g_sum + blockIdx.x * (NCLUS * DDIM / SORT_CTAS);
        z[tid] = 0.0f;
        z[tid + SORT_THREADS] = 0.0f;
    }
    if (blockIdx.x == 0 && tid == 0) g_accum = 0.0f;

    grid_bar();  // all global count atomics complete

    // warp-shuffle prefix over 512 global counts (every CTA, locally)
    const int lane = tid & 31, w = tid >> 5;
    int cnt = g_counts[tid * CSTRIDE];
    int inc = cnt;
#pragma unroll
    for (int o = 1; o < 32; o <<= 1) {
        int v = __shfl_up_sync(0xffffffffu, inc, o);
        if (lane >= o) inc += v;
    }
    if (lane == 31) s_wsum[w] = inc;
    __syncthreads();
    if (w == 0 && lane < 16) {
        int v = s_wsum[lane];
        int s = v;
#pragma unroll
        for (int o = 1; o < 16; o <<= 1) {
            int u = __shfl_up_sync(0x0000ffffu, s, o);
            if (lane >= o) s += u;
        }
        s_wsum[lane] = s - v;   // exclusive warp base
    }
    __syncthreads();
    int excl = s_wsum[w] + (inc - cnt);   // global exclusive offset of cluster tid
    s_off[tid] = excl;
    if (blockIdx.x == 0) {
        g_offsets[tid] = excl;
        g_cnt[tid]     = cnt;
        g_inv[tid]     = 1.0f / (float)(cnt > 0 ? cnt : 1);
    }
    __syncthreads();

    // phase 2: scatter permutation (labels/ranks still in registers)
#pragma unroll
    for (int k = 0; k < SORT_RPT; k++) {
        int i = base + k * SORT_THREADS + tid;
        int c = lab[k];
        g_perm[s_off[c] + s_base[c] + lrk[k]] = i;
    }
}

// ---------------- kernel 2: segmented gather-sum (HBM hot path) -------------
__global__ __launch_bounds__(256) void k_center(const float* __restrict__ M) {
    __shared__ int    sperm[1024];
    __shared__ float4 sred[3][64];
    const int c     = blockIdx.x >> 2;
    const int seg   = blockIdx.x & 3;
    const int t     = threadIdx.x;

    // reset sort counters for the next graph replay (ordered by kernel boundary)
    if (t == 0 && blockIdx.x < NCLUS) g_counts[blockIdx.x * CSTRIDE] = 0;

    const int start = g_offsets[c];
    const int cnt   = g_cnt[c];
    const int s0    = (cnt * seg) >> 2;
    const int s1    = (cnt * (seg + 1)) >> 2;
    const int n     = s1 - s0;
    const int grp   = t >> 6;      // 0..3: row phase
    const int col4  = t & 63;      // float4 column

    const float4* __restrict__ Mv = (const float4*)M;
    float4 a0 = {0,0,0,0}, a1 = {0,0,0,0}, a2 = {0,0,0,0}, a3 = {0,0,0,0};

    if (n <= 1024) {
        for (int r = t; r < n; r += 256) sperm[r] = g_perm[start + s0 + r];
        __syncthreads();
        int r = grp;
        for (; r + 12 < n; r += 16) {
            float4 v0 = __ldcs(&Mv[(size_t)sperm[r]      * 64 + col4]);
            float4 v1 = __ldcs(&Mv[(size_t)sperm[r + 4]  * 64 + col4]);
            float4 v2 = __ldcs(&Mv[(size_t)sperm[r + 8]  * 64 + col4]);
            float4 v3 = __ldcs(&Mv[(size_t)sperm[r + 12] * 64 + col4]);
            a0.x += v0.x; a0.y += v0.y; a0.z += v0.z; a0.w += v0.w;
            a1.x += v1.x; a1.y += v1.y; a1.z += v1.z; a1.w += v1.w;
            a2.x += v2.x; a2.y += v2.y; a2.z += v2.z; a2.w += v2.w;
            a3.x += v3.x; a3.y += v3.y; a3.z += v3.z; a3.w += v3.w;
        }
        for (; r < n; r += 4) {
            float4 v = __ldcs(&Mv[(size_t)sperm[r] * 64 + col4]);
            a0.x += v.x; a0.y += v.y; a0.z += v.z; a0.w += v.w;
        }
    } else {  // safety fallback (statistically unreachable)
        for (int r = grp; r < n; r += 4) {
            float4 v = __ldcs(&Mv[(size_t)g_perm[start + s0 + r] * 64 + col4]);
            a0.x += v.x; a0.y += v.y; a0.z += v.z; a0.w += v.w;
        }
        __syncthreads();
    }

    float4 acc;
    acc.x = (a0.x + a1.x) + (a2.x + a3.x);
    acc.y = (a0.y + a1.y) + (a2.y + a3.y);
    acc.z = (a0.z + a1.z) + (a2.z + a3.z);
    acc.w = (a0.w + a1.w) + (a2.w + a3.w);

    if (grp > 0) sred[grp - 1][col4] = acc;
    __syncthreads();
    if (grp == 0) {
        float4 b0 = sred[0][col4], b1 = sred[1][col4], b2 = sred[2][col4];
        acc.x += b0.x + b1.x + b2.x;
        acc.y += b0.y + b1.y + b2.y;
        acc.z += b0.z + b1.z + b2.z;
        acc.w += b0.w + b1.w + b2.w;
        float* dst = g_sum + c * DDIM + col4 * 4;
        atomicAdd(dst + 0, acc.x);
        atomicAdd(dst + 1, acc.y);
        atomicAdd(dst + 2, acc.z);
        atomicAdd(dst + 3, acc.w);
    }
}

// ---------------- kernel 3: tiled pdist (divide fused into load) + finalize -
#define PT 32
#define DCH 64
#define NT (NCLUS / PT)                 // 16 -> 136 blocks
#define PDIST_BLOCKS (NT * (NT + 1) / 2)
__global__ __launch_bounds__(256) void k_pdist(float* __restrict__ out) {
    __shared__ float Ci[PT][DCH + 1];
    __shared__ float Cj[PT][DCH + 1];
    __shared__ float red[8];

    int b = blockIdx.x;
    int bi = 0, nb = NT;
    while (b >= nb) { b -= nb; bi++; nb--; }
    int bj = bi + b;
    const int i0 = bi * PT, j0 = bj * PT;

    const int tid = threadIdx.x;
    const int tx = tid & 15, ty = tid >> 4;

    float s00 = 0.f, s01 = 0.f, s10 = 0.f, s11 = 0.f;

    for (int dbase = 0; dbase < DDIM; dbase += DCH) {
        for (int idx = tid; idx < PT * DCH; idx += 256) {
            int r = idx / DCH, col = idx % DCH;
            Ci[r][col] = g_sum[(i0 + r) * DDIM + dbase + col] * g_inv[i0 + r];
            Cj[r][col] = g_sum[(j0 + r) * DDIM + dbase + col] * g_inv[j0 + r];
        }
        __syncthreads();
#pragma unroll 8
        for (int d = 0; d < DCH; d++) {
            float ia = Ci[2 * ty + 0][d];
            float ib = Ci[2 * ty + 1][d];
            float ja = Cj[2 * tx + 0][d];
            float jb = Cj[2 * tx + 1][d];
            float d00 = ia - ja; s00 += d00 * d00;
            float d01 = ia - jb; s01 += d01 * d01;
            float d10 = ib - ja; s10 += d10 * d10;
            float d11 = ib - jb; s11 += d11 * d11;
        }
        __syncthreads();
    }

    float local = 0.f;
    {
        int gi0 = i0 + 2 * ty, gi1 = gi0 + 1;
        int gj0 = j0 + 2 * tx, gj1 = gj0 + 1;
        if (gj0 > gi0) local += sqrtf(fmaxf(s00, 1e-12f));
        if (gj1 > gi0) local += sqrtf(fmaxf(s01, 1e-12f));
        if (gj0 > gi1) local += sqrtf(fmaxf(s10, 1e-12f));
        if (gj1 > gi1) local += sqrtf(fmaxf(s11, 1e-12f));
    }
#pragma unroll
    for (int off = 16; off > 0; off >>= 1)
        local += __shfl_down_sync(0xffffffffu, local, off);
    if ((tid & 31) == 0) red[tid >> 5] = local;
    __syncthreads();
    if (tid == 0) {
        float blk = 0.f;
#pragma unroll
        for (int w = 0; w < 8; w++) blk += red[w];
        atomicAdd(&g_accum, blk);
        __threadfence();
        int prev = atomicAdd(&g_done, 1);
        if (prev == PDIST_BLOCKS - 1) {
            g_done = 0;
            out[0] = -g_accum / (float)NPAIRS;
        }
    }
}

extern "C" void kernel_launch(void* const* d_in, const int* in_sizes, int n_in,
                              void* d_out, int out_size) {
    const float* matrix = (const float*)d_in[0];
    const int*   label  = (const int*)d_in[1];
    float* out = (float*)d_out;

    k_sort<<<SORT_CTAS, SORT_THREADS>>>(label);
    k_center<<<CENTER_CTAS, 256>>>(matrix);
    k_pdist<<<PDIST_BLOCKS, 256>>>(out);
}